// round 13
// baseline (speedup 1.0000x reference)
#include <cuda_runtime.h>
#include <cstdint>

// ---------------------------------------------------------------------------
// Problem constants
// ---------------------------------------------------------------------------
#define NN    512
#define TT    64
#define DIN   1024
#define DOUT  1024
#define MTOT  (NN * TT)          // 32768

// GEMM tiling: CTA 128x128, 256 threads, 8x8/thread, KC=32 fully unrolled,
// 3-stage cp.async pipeline, packed fma.rn.f32x2 micro-kernel.
// cp.async for stage kt+2 interleaved into compute k=0..7 (one per k).
#define KC      32
#define KTILES  (DIN / KC)       // 32
#define NSTAGE  3
#define STAGE_BYTES (KC * 128 * 4 * 2)     // A(16KB) + B(16KB) = 32768
#define STAGE_FLOATS (STAGE_BYTES / 4)
#define STG_PITCH   129                    // epilogue staging [o:128][129][m:128]
#define SMEM_BYTES  (NSTAGE * STAGE_BYTES) // 98304 >= 128*129*4 = 66048

// ---------------------------------------------------------------------------
// Device scratch (sanctioned: __device__ globals)
// ---------------------------------------------------------------------------
__device__ float g_at[(size_t)DIN * MTOT];  // 128 MB: A transposed [k][m]
__device__ float g_wt[DIN * DOUT];          // 4 MB: BN-folded W transposed [k][o]
__device__ float g_bstep[DOUT];

// ---------------------------------------------------------------------------
// Inline PTX
// ---------------------------------------------------------------------------
__device__ __forceinline__ uint32_t smem_to_u32(const void* p) {
    uint32_t a;
    asm("{ .reg .u64 t; cvta.to.shared.u64 t, %1; cvt.u32.u64 %0, t; }"
        : "=r"(a) : "l"(p));
    return a;
}

__device__ __forceinline__ void cpasync16(uint32_t s, const void* g) {
    asm volatile("cp.async.cg.shared.global [%0], [%1], 16;"
                 :: "r"(s), "l"(g) : "memory");
}

// Packed dual fp32 FMA: per-half bit-identical to scalar fma.rn.f32.
__device__ __forceinline__ void ffma2(unsigned long long& d,
                                      unsigned long long a,
                                      unsigned long long b) {
    asm("fma.rn.f32x2 %0, %1, %2, %0;" : "+l"(d) : "l"(a), "l"(b));
}

__device__ __forceinline__ unsigned long long pack2(float x) {
    unsigned long long r;
    asm("mov.b64 %0, {%1, %1};" : "=l"(r) : "f"(x));
    return r;
}

__device__ __forceinline__ void unpack2(unsigned long long v, float& lo, float& hi) {
    asm("mov.b64 {%0, %1}, %2;" : "=f"(lo), "=f"(hi) : "l"(v));
}

// ---------------------------------------------------------------------------
// Merged prep (R12): one launch.
//   blockIdx.x <  8192 : transpose A[m][k] -> At[k][m]
//   blockIdx.x >= 8192 : fold BN into W -> Wt[k][o] (+ b_step)
// ---------------------------------------------------------------------------
__global__ __launch_bounds__(256)
void prep_kernel(const float* __restrict__ A,
                 const float* __restrict__ w,
                 const float* __restrict__ bias,
                 const float* __restrict__ gamma,
                 const float* __restrict__ beta,
                 const float* __restrict__ mean,
                 const float* __restrict__ var) {
    __shared__ float s[32][129];
    const int tid = threadIdx.x;

    if (blockIdx.x < 8192) {
        const int bx = blockIdx.x;
        const int k0 = (bx & 31) * 32;           // 32 k-tiles
        const int m0 = (bx >> 5) * 128;          // 256 m-tiles
#pragma unroll
        for (int i = 0; i < 4; i++) {
            const int c = tid + i * 256;
            const int m = c >> 3, kq = c & 7;
            const float4 v = *(const float4*)(A + (size_t)(m0 + m) * DIN + k0 + kq * 4);
            s[kq * 4 + 0][m] = v.x;
            s[kq * 4 + 1][m] = v.y;
            s[kq * 4 + 2][m] = v.z;
            s[kq * 4 + 3][m] = v.w;
        }
        __syncthreads();
#pragma unroll
        for (int i = 0; i < 4; i++) {
            const int c = tid + i * 256;
            const int k = c >> 5, mq = c & 31;
            float4 v;
            v.x = s[k][mq * 4 + 0];
            v.y = s[k][mq * 4 + 1];
            v.z = s[k][mq * 4 + 2];
            v.w = s[k][mq * 4 + 3];
            *(float4*)(g_at + (size_t)(k0 + k) * MTOT + m0 + mq * 4) = v;
        }
    } else {
        const int bx = blockIdx.x - 8192;        // 0..1023
        const int k0 = (bx & 31) * 32;
        const int o0 = (bx >> 5) * 32;
        __shared__ float rat[32];
        if (tid < 32) {
            const int o = o0 + tid;
            const float ratio = gamma[o] / sqrtf(var[o]);
            rat[tid] = ratio;
            if (k0 == 0) {
                g_bstep[o] = ((bias[o] - mean[o]) * ratio + beta[o]) * (1.0f / (float)TT);
            }
        }
        __syncthreads();
#pragma unroll
        for (int i = 0; i < 4; i++) {
            const int c = tid + i * 256;
            const int oc = c >> 5, kx = c & 31;
            s[oc][kx] = w[(size_t)(o0 + oc) * DIN + k0 + kx] * rat[oc];
        }
        __syncthreads();
#pragma unroll
        for (int i = 0; i < 4; i++) {
            const int c = tid + i * 256;
            const int k = c >> 5, ox = c & 31;
            g_wt[(size_t)(k0 + k) * DOUT + o0 + ox] = s[ox][k];
        }
    }
}

// ---------------------------------------------------------------------------
// Prologue stage loader (burst form; used only for stages 0 and 1).
// ---------------------------------------------------------------------------
__device__ __forceinline__ void load_stage(uint32_t sbu, int stage, int kt,
                                           int m0, int o0, int tid) {
    const uint32_t st = sbu + stage * STAGE_BYTES;
    const int k0 = kt * KC;
    const float* gA = g_at + (size_t)k0 * MTOT + m0;
    const float* gB = g_wt + (size_t)k0 * DOUT + o0;
#pragma unroll
    for (int i = 0; i < 4; i++) {
        const int c = tid + i * 256;
        const int k = c >> 5, cg = c & 31;
        cpasync16(st + k * 512 + cg * 16, gA + (size_t)k * MTOT + cg * 4);
        cpasync16(st + 16384 + k * 512 + cg * 16, gB + (size_t)k * DOUT + cg * 4);
    }
    asm volatile("cp.async.commit_group;" ::: "memory");
}

// ---------------------------------------------------------------------------
// Fused SGEMM + IF scan: packed-FFMA2, KC=32 fully unrolled, 3-stage,
// cp.async for stage kt+2 interleaved at k=0..7, ONE barrier per tile.
// Per tile: wait_group -> syncthreads -> compute(+loads) -> commit.
// Safety: in-order group completion => after wait_group 1 only the newest
// group may pend => stage kt complete; barrier publishes it CTA-wide and
// separates tile kt-1's reads of buffer (kt+2)%3 from this tile's writes.
// Chain: acc=0, k ascending, one fma.rn per k -> outputs bit-identical to
// R1/R5/R6/R8/R9/R10/R12 (rel_err 8.103138e-4).
// ---------------------------------------------------------------------------
__global__ __launch_bounds__(256, 2)
void gemm_if_kernel(float* __restrict__ spike_out,
                    float* __restrict__ count_out) {
    extern __shared__ __align__(16) float smem[];
    const uint32_t sbu = smem_to_u32(smem);

    const int tid  = threadIdx.x;
    const int warp = tid >> 5;
    const int lane = tid & 31;
    const int wr   = warp >> 1;
    const int wc   = warp & 1;
    const int rbase = wr * 32 + ((lane >> 3) << 2);
    const int cbase = wc * 64 + ((lane & 7) << 2);

    const int o0 = blockIdx.x * 128;        // 8 o-tiles (A tiles L2-shared)
    const int m0 = blockIdx.y * 128;        // 256 m-tiles

    unsigned long long acc2[8][4];
#pragma unroll
    for (int i = 0; i < 8; i++)
#pragma unroll
        for (int p = 0; p < 4; p++) acc2[i][p] = 0ull;

    load_stage(sbu, 0, 0, m0, o0, tid);
    load_stage(sbu, 1, 1, m0, o0, tid);

    int stage = 0;
    for (int kt = 0; kt < KTILES; kt++) {
        if (kt + 1 < KTILES)
            asm volatile("cp.async.wait_group 1;" ::: "memory");
        else
            asm volatile("cp.async.wait_group 0;" ::: "memory");
        __syncthreads();                     // publish stage kt; fence buffer reuse

        // Next-next stage pointers (writes embedded below at k=0..7)
        int ns = stage + 2; if (ns >= NSTAGE) ns -= NSTAGE;
        const uint32_t stn = sbu + ns * STAGE_BYTES;
        const float* gAn = g_at + (size_t)(kt + 2) * KC * MTOT + m0;
        const float* gBn = g_wt + (size_t)(kt + 2) * KC * DOUT + o0;
        const bool doload = (kt + 2 < KTILES);

        const float* As = smem + stage * STAGE_FLOATS;
        const float* Bs = As + KC * 128;

#pragma unroll
        for (int k = 0; k < KC; k++) {
            if (k < 8 && doload) {
                const int ci = (k < 4) ? k : (k - 4);
                const int c = tid + ci * 256;
                const int kk = c >> 5, cg = c & 31;
                if (k < 4)
                    cpasync16(stn + kk * 512 + cg * 16,
                              gAn + (size_t)kk * MTOT + cg * 4);
                else
                    cpasync16(stn + 16384 + kk * 512 + cg * 16,
                              gBn + (size_t)kk * DOUT + cg * 4);
            }
            float a[8];
            *(float4*)&a[0] = *(const float4*)&As[k * 128 + rbase];
            *(float4*)&a[4] = *(const float4*)&As[k * 128 + rbase + 16];
            const ulonglong2 bv0 = *(const ulonglong2*)&Bs[k * 128 + cbase];
            const ulonglong2 bv1 = *(const ulonglong2*)&Bs[k * 128 + cbase + 32];
#pragma unroll
            for (int i = 0; i < 8; i++) {
                const unsigned long long a2 = pack2(a[i]);
                ffma2(acc2[i][0], a2, bv0.x);
                ffma2(acc2[i][1], a2, bv0.y);
                ffma2(acc2[i][2], a2, bv1.x);
                ffma2(acc2[i][3], a2, bv1.y);
            }
        }
        if (doload)
            asm volatile("cp.async.commit_group;" ::: "memory");

        stage = stage + 1; if (stage >= NSTAGE) stage -= NSTAGE;
    }
    __syncthreads();   // all compute done before reusing smem for staging

    // ---- Epilogue: unpack, stage [o_local][m_local] (pitch 129), IF scan ----
    float* stg = smem;
#pragma unroll
    for (int i = 0; i < 8; i++) {
        const int ml = rbase + (i & 3) + ((i >> 2) << 4);
#pragma unroll
        for (int p = 0; p < 4; p++) {
            float lo, hi;
            unpack2(acc2[i][p], lo, hi);
            const int ol = cbase + ((2 * p) & 3) + ((p >> 1) << 5);
            stg[ol * STG_PITCH + ml]       = lo;
            stg[(ol + 1) * STG_PITCH + ml] = hi;
        }
    }
    __syncthreads();

    // 256 tasks: o_l in [0,128) x n-group {0,1}; m_l = nl*64 + t
    const int ol = tid & 127;
    const int nl = tid >> 7;
    const int n  = (m0 >> 6) + nl;
    const int og = o0 + ol;
    const float bs = g_bstep[og];
    const float* col = stg + ol * STG_PITCH + nl * 64;
    float* so = spike_out + (size_t)n * TT * DOUT + og;

    float pot = 0.0f, cnt = 0.0f;
#pragma unroll 8
    for (int t = 0; t < TT; t++) {
        pot = (pot + col[t]) + bs;          // left-assoc, identical to R1 scan
        const float spk = (pot >= 1.0f) ? 1.0f : 0.0f;
        so[(size_t)t * DOUT] = spk;
        pot -= spk;
        cnt += spk;
    }
    count_out[(size_t)n * DOUT + og] = cnt;
}

// ---------------------------------------------------------------------------
// Launch
// ---------------------------------------------------------------------------
extern "C" void kernel_launch(void* const* d_in, const int* in_sizes, int n_in,
                              void* d_out, int out_size) {
    (void)in_sizes; (void)n_in; (void)out_size;

    const float* x_st  = (const float*)d_in[0];  // (512, 64, 1024) binary
    const float* w     = (const float*)d_in[2];
    const float* bias  = (const float*)d_in[3];
    const float* gamma = (const float*)d_in[4];
    const float* beta  = (const float*)d_in[5];
    const float* mean  = (const float*)d_in[6];
    const float* var   = (const float*)d_in[7];

    float* out       = (float*)d_out;
    float* spike_out = out;                                 // 512*64*1024
    float* count_out = out + (size_t)MTOT * DOUT;           // 512*1024

    prep_kernel<<<8192 + 1024, 256>>>(x_st, w, bias, gamma, beta, mean, var);

    cudaFuncSetAttribute(gemm_if_kernel,
                         cudaFuncAttributeMaxDynamicSharedMemorySize, SMEM_BYTES);

    dim3 grid(DOUT / 128, MTOT / 128);                      // (8, 256)
    gemm_if_kernel<<<grid, 256, SMEM_BYTES>>>(spike_out, count_out);
}

// round 14
// speedup vs baseline: 1.0241x; 1.0241x over previous
#include <cuda_runtime.h>
#include <cstdint>

// ---------------------------------------------------------------------------
// Problem constants
// ---------------------------------------------------------------------------
#define NN    512
#define TT    64
#define DIN   1024
#define DOUT  1024
#define MTOT  (NN * TT)          // 32768

// GEMM tiling (R12 config — measured optimum): CTA 128x128, 256 threads,
// 8x8/thread, KC=32 fully unrolled, 3-stage cp.async pipeline,
// packed fma.rn.f32x2 micro-kernel, burst stage loads, load-before-wait.
#define KC      32
#define KTILES  (DIN / KC)       // 32
#define NSTAGE  3
#define STAGE_BYTES (KC * 128 * 4 * 2)     // A(16KB) + B(16KB) = 32768
#define STAGE_FLOATS (STAGE_BYTES / 4)
#define STG_PITCH   129                    // epilogue staging [o:128][129][m:128]
#define SMEM_BYTES  (NSTAGE * STAGE_BYTES) // 98304 >= 128*129*4 = 66048

// ---------------------------------------------------------------------------
// Device scratch (sanctioned: __device__ globals)
// ---------------------------------------------------------------------------
__device__ float g_at[(size_t)DIN * MTOT];  // 128 MB: A transposed [k][m]
__device__ float g_wt[DIN * DOUT];          // 4 MB: BN-folded W transposed [k][o]
__device__ float g_bstep[DOUT];

// ---------------------------------------------------------------------------
// Inline PTX
// ---------------------------------------------------------------------------
__device__ __forceinline__ uint32_t smem_to_u32(const void* p) {
    uint32_t a;
    asm("{ .reg .u64 t; cvta.to.shared.u64 t, %1; cvt.u32.u64 %0, t; }"
        : "=r"(a) : "l"(p));
    return a;
}

__device__ __forceinline__ void cpasync16(uint32_t s, const void* g) {
    asm volatile("cp.async.cg.shared.global [%0], [%1], 16;"
                 :: "r"(s), "l"(g) : "memory");
}

// Packed dual fp32 FMA: per-half bit-identical to scalar fma.rn.f32.
__device__ __forceinline__ void ffma2(unsigned long long& d,
                                      unsigned long long a,
                                      unsigned long long b) {
    asm("fma.rn.f32x2 %0, %1, %2, %0;" : "+l"(d) : "l"(a), "l"(b));
}

__device__ __forceinline__ unsigned long long pack2(float x) {
    unsigned long long r;
    asm("mov.b64 %0, {%1, %1};" : "=l"(r) : "f"(x));
    return r;
}

__device__ __forceinline__ void unpack2(unsigned long long v, float& lo, float& hi) {
    asm("mov.b64 {%0, %1}, %2;" : "=f"(lo), "=f"(hi) : "l"(v));
}

// ---------------------------------------------------------------------------
// Merged prep: one launch.
//   blockIdx.x <  8192 : transpose A[m][k] -> At[k][m] (128m x 32k tiles,
//                        float4 both gmem sides)
//   blockIdx.x >= 8192 : fold BN into W and transpose -> Wt[k][o] (+ b_step)
// ---------------------------------------------------------------------------
__global__ __launch_bounds__(256)
void prep_kernel(const float* __restrict__ A,
                 const float* __restrict__ w,
                 const float* __restrict__ bias,
                 const float* __restrict__ gamma,
                 const float* __restrict__ beta,
                 const float* __restrict__ mean,
                 const float* __restrict__ var) {
    __shared__ float s[32][129];
    const int tid = threadIdx.x;

    if (blockIdx.x < 8192) {
        // ---- A transpose: tile (k0, m0) ----
        const int bx = blockIdx.x;
        const int k0 = (bx & 31) * 32;           // 32 k-tiles
        const int m0 = (bx >> 5) * 128;          // 256 m-tiles
#pragma unroll
        for (int i = 0; i < 4; i++) {
            const int c = tid + i * 256;
            const int m = c >> 3, kq = c & 7;
            const float4 v = *(const float4*)(A + (size_t)(m0 + m) * DIN + k0 + kq * 4);
            s[kq * 4 + 0][m] = v.x;
            s[kq * 4 + 1][m] = v.y;
            s[kq * 4 + 2][m] = v.z;
            s[kq * 4 + 3][m] = v.w;
        }
        __syncthreads();
#pragma unroll
        for (int i = 0; i < 4; i++) {
            const int c = tid + i * 256;
            const int k = c >> 5, mq = c & 31;
            float4 v;
            v.x = s[k][mq * 4 + 0];
            v.y = s[k][mq * 4 + 1];
            v.z = s[k][mq * 4 + 2];
            v.w = s[k][mq * 4 + 3];
            *(float4*)(g_at + (size_t)(k0 + k) * MTOT + m0 + mq * 4) = v;
        }
    } else {
        // ---- W fold+transpose: 32x32 tile (k0, o0) ----
        const int bx = blockIdx.x - 8192;        // 0..1023
        const int k0 = (bx & 31) * 32;
        const int o0 = (bx >> 5) * 32;
        __shared__ float rat[32];
        if (tid < 32) {
            const int o = o0 + tid;
            const float ratio = gamma[o] / sqrtf(var[o]);
            rat[tid] = ratio;
            if (k0 == 0) {
                g_bstep[o] = ((bias[o] - mean[o]) * ratio + beta[o]) * (1.0f / (float)TT);
            }
        }
        __syncthreads();
#pragma unroll
        for (int i = 0; i < 4; i++) {
            const int c = tid + i * 256;
            const int oc = c >> 5, kx = c & 31;
            s[oc][kx] = w[(size_t)(o0 + oc) * DIN + k0 + kx] * rat[oc];
        }
        __syncthreads();
#pragma unroll
        for (int i = 0; i < 4; i++) {
            const int c = tid + i * 256;
            const int k = c >> 5, ox = c & 31;
            g_wt[(size_t)(k0 + k) * DOUT + o0 + ox] = s[ox][k];
        }
    }
}

// ---------------------------------------------------------------------------
// Stage loader: cp.async straight into [k][row] layout (burst form).
// ---------------------------------------------------------------------------
__device__ __forceinline__ void load_stage(uint32_t sbu, int stage, int kt,
                                           int m0, int o0, int tid) {
    const uint32_t st = sbu + stage * STAGE_BYTES;
    const int k0 = kt * KC;
    const float* gA = g_at + (size_t)k0 * MTOT + m0;
    const float* gB = g_wt + (size_t)k0 * DOUT + o0;
#pragma unroll
    for (int i = 0; i < 4; i++) {
        const int c = tid + i * 256;
        const int k = c >> 5, cg = c & 31;
        cpasync16(st + k * 512 + cg * 16, gA + (size_t)k * MTOT + cg * 4);
        cpasync16(st + 16384 + k * 512 + cg * 16, gB + (size_t)k * DOUT + cg * 4);
    }
    asm volatile("cp.async.commit_group;" ::: "memory");
}

// ---------------------------------------------------------------------------
// Fused SGEMM + IF scan (R12 config, verbatim — measured optimum):
// packed-FFMA2, KC=32 fully unrolled, 3-stage, load-before-wait.
// Chain: acc=0, k ascending, one fma.rn per k -> outputs bit-identical to
// R1/R5/R6/R8/R9/R10/R12 (rel_err 8.103138e-4).
// ---------------------------------------------------------------------------
__global__ __launch_bounds__(256, 2)
void gemm_if_kernel(float* __restrict__ spike_out,
                    float* __restrict__ count_out) {
    extern __shared__ __align__(16) float smem[];
    const uint32_t sbu = smem_to_u32(smem);

    const int tid  = threadIdx.x;
    const int warp = tid >> 5;
    const int lane = tid & 31;
    const int wr   = warp >> 1;
    const int wc   = warp & 1;
    const int rbase = wr * 32 + ((lane >> 3) << 2);
    const int cbase = wc * 64 + ((lane & 7) << 2);

    const int o0 = blockIdx.x * 128;        // 8 o-tiles (A tiles L2-shared)
    const int m0 = blockIdx.y * 128;        // 256 m-tiles

    unsigned long long acc2[8][4];
#pragma unroll
    for (int i = 0; i < 8; i++)
#pragma unroll
        for (int p = 0; p < 4; p++) acc2[i][p] = 0ull;

    load_stage(sbu, 0, 0, m0, o0, tid);
    load_stage(sbu, 1, 1, m0, o0, tid);

    int stage = 0;
    for (int kt = 0; kt < KTILES; kt++) {
        __syncthreads();                     // stage (kt+2)%3's readers done

        if (kt + 2 < KTILES) {
            int ns = stage + 2; if (ns >= NSTAGE) ns -= NSTAGE;
            load_stage(sbu, ns, kt + 2, m0, o0, tid);
            asm volatile("cp.async.wait_group 2;" ::: "memory");
        } else {
            asm volatile("cp.async.wait_group 0;" ::: "memory");
        }
        __syncthreads();                     // stage kt visible to all threads

        const float* As = smem + stage * STAGE_FLOATS;
        const float* Bs = As + KC * 128;

#pragma unroll
        for (int k = 0; k < KC; k++) {
            float a[8];
            *(float4*)&a[0] = *(const float4*)&As[k * 128 + rbase];
            *(float4*)&a[4] = *(const float4*)&As[k * 128 + rbase + 16];
            const ulonglong2 bv0 = *(const ulonglong2*)&Bs[k * 128 + cbase];
            const ulonglong2 bv1 = *(const ulonglong2*)&Bs[k * 128 + cbase + 32];
#pragma unroll
            for (int i = 0; i < 8; i++) {
                const unsigned long long a2 = pack2(a[i]);
                ffma2(acc2[i][0], a2, bv0.x);
                ffma2(acc2[i][1], a2, bv0.y);
                ffma2(acc2[i][2], a2, bv1.x);
                ffma2(acc2[i][3], a2, bv1.y);
            }
        }

        stage = stage + 1; if (stage >= NSTAGE) stage -= NSTAGE;
    }
    __syncthreads();   // all compute done before reusing smem for staging

    // ---- Epilogue: unpack, stage [o_local][m_local] (pitch 129), IF scan ----
    float* stg = smem;
#pragma unroll
    for (int i = 0; i < 8; i++) {
        const int ml = rbase + (i & 3) + ((i >> 2) << 4);
#pragma unroll
        for (int p = 0; p < 4; p++) {
            float lo, hi;
            unpack2(acc2[i][p], lo, hi);
            const int ol = cbase + ((2 * p) & 3) + ((p >> 1) << 5);
            stg[ol * STG_PITCH + ml]       = lo;
            stg[(ol + 1) * STG_PITCH + ml] = hi;
        }
    }
    __syncthreads();

    // 256 tasks: o_l in [0,128) x n-group {0,1}; m_l = nl*64 + t
    const int ol = tid & 127;
    const int nl = tid >> 7;
    const int n  = (m0 >> 6) + nl;
    const int og = o0 + ol;
    const float bs = g_bstep[og];
    const float* col = stg + ol * STG_PITCH + nl * 64;
    float* so = spike_out + (size_t)n * TT * DOUT + og;

    float pot = 0.0f, cnt = 0.0f;
#pragma unroll 8
    for (int t = 0; t < TT; t++) {
        pot = (pot + col[t]) + bs;          // left-assoc, identical to R1 scan
        const float spk = (pot >= 1.0f) ? 1.0f : 0.0f;
        so[(size_t)t * DOUT] = spk;
        pot -= spk;
        cnt += spk;
    }
    count_out[(size_t)n * DOUT + og] = cnt;
}

// ---------------------------------------------------------------------------
// Launch
// ---------------------------------------------------------------------------
extern "C" void kernel_launch(void* const* d_in, const int* in_sizes, int n_in,
                              void* d_out, int out_size) {
    (void)in_sizes; (void)n_in; (void)out_size;

    const float* x_st  = (const float*)d_in[0];  // (512, 64, 1024) binary
    const float* w     = (const float*)d_in[2];
    const float* bias  = (const float*)d_in[3];
    const float* gamma = (const float*)d_in[4];
    const float* beta  = (const float*)d_in[5];
    const float* mean  = (const float*)d_in[6];
    const float* var   = (const float*)d_in[7];

    float* out       = (float*)d_out;
    float* spike_out = out;                                 // 512*64*1024
    float* count_out = out + (size_t)MTOT * DOUT;           // 512*1024

    prep_kernel<<<8192 + 1024, 256>>>(x_st, w, bias, gamma, beta, mean, var);

    cudaFuncSetAttribute(gemm_if_kernel,
                         cudaFuncAttributeMaxDynamicSharedMemorySize, SMEM_BYTES);

    dim3 grid(DOUT / 128, MTOT / 128);                      // (8, 256)
    gemm_if_kernel<<<grid, 256, SMEM_BYTES>>>(spike_out, count_out);
}